// round 5
// baseline (speedup 1.0000x reference)
#include <cuda_runtime.h>

#define S_LEN 4096
#define DM    512
#define DF    2048
#define NH    8
#define DH    64

// scratch (no allocations allowed)
__device__ float g_q   [(size_t)S_LEN * DM];
__device__ float g_k   [(size_t)S_LEN * DM];
__device__ float g_v   [(size_t)S_LEN * DM];
__device__ float g_attn[(size_t)S_LEN * DM];
__device__ float g_tmp [(size_t)S_LEN * DM];
__device__ float g_x1  [(size_t)S_LEN * DM];
__device__ float g_hid [(size_t)S_LEN * DF];

// ---------------- double-buffered SGEMM: C[M,N]=A[M,K]@B[K,N]+bias (+relu)(+res)
template<int BN, int TN>
__device__ __forceinline__ void gemm_body(
    const float* __restrict__ A, const float* __restrict__ B,
    const float* __restrict__ bias, const float* __restrict__ res,
    float* __restrict__ C, int N, int K, int relu, int bm, int bn)
{
    constexpr int BK = 16, TM = 8, NT = 256;
    constexpr int BN4 = BN / 4;
    constexpr int BL = (BK * BN / 4) / NT;   // B float4 loads/thread

    __shared__ float As[2][BK][128];
    __shared__ float Bs[2][BK][BN];

    const int tid = threadIdx.x;
    const int tx = tid & 15, ty = tid >> 4;

    float4 areg[2], breg[BL];

    #pragma unroll
    for (int r = 0; r < 2; r++) {
        int id = tid + NT * r, arow = id >> 2, akc = id & 3;
        areg[r] = *(const float4*)(A + (size_t)(bm + arow) * K + akc * 4);
    }
    #pragma unroll
    for (int r = 0; r < BL; r++) {
        int id = tid + NT * r, brow = id / BN4, bnc = id % BN4;
        breg[r] = *(const float4*)(B + (size_t)brow * N + bn + bnc * 4);
    }
    #pragma unroll
    for (int r = 0; r < 2; r++) {
        int id = tid + NT * r, arow = id >> 2, akc = id & 3;
        As[0][akc*4+0][arow] = areg[r].x; As[0][akc*4+1][arow] = areg[r].y;
        As[0][akc*4+2][arow] = areg[r].z; As[0][akc*4+3][arow] = areg[r].w;
    }
    #pragma unroll
    for (int r = 0; r < BL; r++) {
        int id = tid + NT * r, brow = id / BN4, bnc = id % BN4;
        *(float4*)(&Bs[0][brow][bnc * 4]) = breg[r];
    }
    __syncthreads();

    float acc[TM][TN];
    #pragma unroll
    for (int i = 0; i < TM; i++)
        #pragma unroll
        for (int j = 0; j < TN; j++) acc[i][j] = 0.f;

    const int nk = K / BK;
    int cur = 0;
    for (int kt = 0; kt < nk; kt++) {
        if (kt + 1 < nk) {
            int ko = (kt + 1) * BK;
            #pragma unroll
            for (int r = 0; r < 2; r++) {
                int id = tid + NT * r, arow = id >> 2, akc = id & 3;
                areg[r] = *(const float4*)(A + (size_t)(bm + arow) * K + ko + akc * 4);
            }
            #pragma unroll
            for (int r = 0; r < BL; r++) {
                int id = tid + NT * r, brow = id / BN4, bnc = id % BN4;
                breg[r] = *(const float4*)(B + (size_t)(ko + brow) * N + bn + bnc * 4);
            }
        }
        #pragma unroll
        for (int kk = 0; kk < BK; kk++) {
            float af[TM], bf[TN];
            float4 a0 = *(const float4*)(&As[cur][kk][ty * 8]);
            float4 a1 = *(const float4*)(&As[cur][kk][ty * 8 + 4]);
            af[0]=a0.x; af[1]=a0.y; af[2]=a0.z; af[3]=a0.w;
            af[4]=a1.x; af[5]=a1.y; af[6]=a1.z; af[7]=a1.w;
            #pragma unroll
            for (int jb = 0; jb < TN / 4; jb++) {
                float4 b0 = *(const float4*)(&Bs[cur][kk][tx * TN + jb * 4]);
                bf[jb*4+0]=b0.x; bf[jb*4+1]=b0.y; bf[jb*4+2]=b0.z; bf[jb*4+3]=b0.w;
            }
            #pragma unroll
            for (int i = 0; i < TM; i++)
                #pragma unroll
                for (int j = 0; j < TN; j++)
                    acc[i][j] += af[i] * bf[j];
        }
        __syncthreads();
        if (kt + 1 < nk) {
            int nb = cur ^ 1;
            #pragma unroll
            for (int r = 0; r < 2; r++) {
                int id = tid + NT * r, arow = id >> 2, akc = id & 3;
                As[nb][akc*4+0][arow] = areg[r].x; As[nb][akc*4+1][arow] = areg[r].y;
                As[nb][akc*4+2][arow] = areg[r].z; As[nb][akc*4+3][arow] = areg[r].w;
            }
            #pragma unroll
            for (int r = 0; r < BL; r++) {
                int id = tid + NT * r, brow = id / BN4, bnc = id % BN4;
                *(float4*)(&Bs[nb][brow][bnc * 4]) = breg[r];
            }
            cur = nb;
            __syncthreads();
        }
    }

    #pragma unroll
    for (int i = 0; i < TM; i++) {
        int row = bm + ty * TM + i;
        #pragma unroll
        for (int jb = 0; jb < TN / 4; jb++) {
            int col = bn + tx * TN + jb * 4;
            float4 bv = *(const float4*)(bias + col);
            float4 r;
            r.x = acc[i][jb*4+0] + bv.x; r.y = acc[i][jb*4+1] + bv.y;
            r.z = acc[i][jb*4+2] + bv.z; r.w = acc[i][jb*4+3] + bv.w;
            if (relu) {
                r.x = fmaxf(r.x,0.f); r.y = fmaxf(r.y,0.f);
                r.z = fmaxf(r.z,0.f); r.w = fmaxf(r.w,0.f);
            }
            if (res) {
                float4 rv = *(const float4*)(res + (size_t)row * N + col);
                r.x += rv.x; r.y += rv.y; r.z += rv.z; r.w += rv.w;
            }
            *(float4*)(C + (size_t)row * N + col) = r;
        }
    }
}

__global__ void __launch_bounds__(256, 2) k_qkv(
    const float* __restrict__ x,
    const float* __restrict__ wq, const float* __restrict__ bq,
    const float* __restrict__ wk, const float* __restrict__ bk,
    const float* __restrict__ wv, const float* __restrict__ bv,
    float* __restrict__ q, float* __restrict__ k, float* __restrict__ v)
{
    const float* W; const float* bb; float* C;
    if (blockIdx.z == 0)      { W = wq; bb = bq; C = q; }
    else if (blockIdx.z == 1) { W = wk; bb = bk; C = k; }
    else                      { W = wv; bb = bv; C = v; }
    gemm_body<64, 4>(x, W, bb, nullptr, C, DM, DM, 0, blockIdx.y * 128, blockIdx.x * 64);
}

__global__ void __launch_bounds__(256, 2) k_gemm128(
    const float* __restrict__ A, const float* __restrict__ B,
    const float* __restrict__ bias, const float* __restrict__ res,
    float* __restrict__ C, int N, int K, int relu)
{
    gemm_body<128, 8>(A, B, bias, res, C, N, K, relu, blockIdx.y * 128, blockIdx.x * 128);
}

// ---------------- flash attention: grid (S/128, H), 256 thr, 100KB smem ------
#define FLASH_SMEM (64 * (132 + 68 + 68 + 132) * 4)

__global__ void __launch_bounds__(256, 2) k_flash(
    const float* __restrict__ q, const float* __restrict__ k,
    const float* __restrict__ v, const int* __restrict__ mask,
    float* __restrict__ out)
{
    extern __shared__ float sm[];
    float* Qt = sm;                 // [64][132] transposed
    float* Ks = sm + 64 * 132;      // [64][68]
    float* Vs = Ks + 64 * 68;       // [64][68]
    float* Pt = Vs + 64 * 68;       // [64][132] transposed

    const int tid = threadIdx.x;
    const int tr = tid >> 4, tc = tid & 15;
    const int row0 = blockIdx.x * 128;
    const int dc0 = blockIdx.y * DH;

    #pragma unroll
    for (int r = 0; r < 8; r++) {
        int id = tid + 256 * r, row = id >> 4, c4 = id & 15;
        float4 t4 = *(const float4*)(q + (size_t)(row0 + row) * DM + dc0 + c4 * 4);
        Qt[(c4*4+0)*132+row] = t4.x; Qt[(c4*4+1)*132+row] = t4.y;
        Qt[(c4*4+2)*132+row] = t4.z; Qt[(c4*4+3)*132+row] = t4.w;
    }

    float acc[8][4], l[8];
    #pragma unroll
    for (int i = 0; i < 8; i++) {
        l[i] = 0.f;
        #pragma unroll
        for (int j = 0; j < 4; j++) acc[i][j] = 0.f;
    }

    for (int t0 = 0; t0 < S_LEN; t0 += 64) {
        __syncthreads();
        #pragma unroll
        for (int r = 0; r < 4; r++) {
            int id = tid + 256 * r, row = id >> 4, c4 = id & 15;
            *(float4*)(Ks + row * 68 + c4 * 4) =
                *(const float4*)(k + (size_t)(t0 + row) * DM + dc0 + c4 * 4);
            *(float4*)(Vs + row * 68 + c4 * 4) =
                *(const float4*)(v + (size_t)(t0 + row) * DM + dc0 + c4 * 4);
        }
        __syncthreads();

        float s[8][4];
        #pragma unroll
        for (int i = 0; i < 8; i++)
            #pragma unroll
            for (int j = 0; j < 4; j++) s[i][j] = 0.f;

        #pragma unroll 2
        for (int dcb = 0; dcb < 16; dcb++) {
            float kreg[4][4];
            #pragma unroll
            for (int j = 0; j < 4; j++) {
                float4 kf = *(const float4*)(Ks + (4*tc + j) * 68 + dcb * 4);
                kreg[j][0]=kf.x; kreg[j][1]=kf.y; kreg[j][2]=kf.z; kreg[j][3]=kf.w;
            }
            #pragma unroll
            for (int m = 0; m < 4; m++) {
                const float* qp = Qt + (dcb*4 + m) * 132 + 8 * tr;
                float4 qa = *(const float4*)qp;
                float4 qb = *(const float4*)(qp + 4);
                float qf[8] = {qa.x,qa.y,qa.z,qa.w,qb.x,qb.y,qb.z,qb.w};
                #pragma unroll
                for (int i = 0; i < 8; i++)
                    #pragma unroll
                    for (int j = 0; j < 4; j++)
                        s[i][j] += qf[i] * kreg[j][m];
            }
        }

        float p[8][4];
        #pragma unroll
        for (int i = 0; i < 8; i++) {
            int4 mv = *(const int4*)(mask + (size_t)(row0 + 8*tr + i) * S_LEN + t0 + 4*tc);
            p[i][0] = mv.x ? __expf(s[i][0]) : 0.f;
            p[i][1] = mv.y ? __expf(s[i][1]) : 0.f;
            p[i][2] = mv.z ? __expf(s[i][2]) : 0.f;
            p[i][3] = mv.w ? __expf(s[i][3]) : 0.f;
            l[i] += p[i][0] + p[i][1] + p[i][2] + p[i][3];
        }
        #pragma unroll
        for (int j = 0; j < 4; j++) {
            float* pp = Pt + (4*tc + j) * 132 + 8 * tr;
            *(float4*)pp       = make_float4(p[0][j], p[1][j], p[2][j], p[3][j]);
            *(float4*)(pp + 4) = make_float4(p[4][j], p[5][j], p[6][j], p[7][j]);
        }
        __syncthreads();

        #pragma unroll 4
        for (int t = 0; t < 64; t++) {
            const float* pp = Pt + t * 132 + 8 * tr;
            float4 pa = *(const float4*)pp;
            float4 pb = *(const float4*)(pp + 4);
            float4 vf = *(const float4*)(Vs + t * 68 + 4 * tc);
            float pf[8] = {pa.x,pa.y,pa.z,pa.w,pb.x,pb.y,pb.z,pb.w};
            #pragma unroll
            for (int i = 0; i < 8; i++) {
                acc[i][0] += pf[i] * vf.x; acc[i][1] += pf[i] * vf.y;
                acc[i][2] += pf[i] * vf.z; acc[i][3] += pf[i] * vf.w;
            }
        }
    }

    #pragma unroll
    for (int i = 0; i < 8; i++) {
        float li = l[i];
        li += __shfl_xor_sync(0xffffffffu, li, 1);
        li += __shfl_xor_sync(0xffffffffu, li, 2);
        li += __shfl_xor_sync(0xffffffffu, li, 4);
        li += __shfl_xor_sync(0xffffffffu, li, 8);
        float inv = 1.0f / li;
        *(float4*)(out + (size_t)(row0 + 8*tr + i) * DM + dc0 + 4*tc) =
            make_float4(acc[i][0]*inv, acc[i][1]*inv, acc[i][2]*inv, acc[i][3]*inv);
    }
}

// ---------------- layernorm: one 128-thread block per row --------------------
__global__ void __launch_bounds__(128) k_ln(
    const float* __restrict__ in, const float* __restrict__ g,
    const float* __restrict__ b, float* __restrict__ out)
{
    const int row = blockIdx.x, tid = threadIdx.x;
    float4 x = *(const float4*)(in + (size_t)row * DM + tid * 4);
    float s  = x.x + x.y + x.z + x.w;
    float ss = x.x*x.x + x.y*x.y + x.z*x.z + x.w*x.w;
    #pragma unroll
    for (int m = 16; m > 0; m >>= 1) {
        s  += __shfl_xor_sync(0xffffffffu, s, m);
        ss += __shfl_xor_sync(0xffffffffu, ss, m);
    }
    __shared__ float red[8];
    int wid = tid >> 5, lane = tid & 31;
    if (lane == 0) { red[wid] = s; red[4 + wid] = ss; }
    __syncthreads();
    s  = red[0] + red[1] + red[2] + red[3];
    ss = red[4] + red[5] + red[6] + red[7];
    float mu = s * (1.f / DM);
    float var = ss * (1.f / DM) - mu * mu;
    float rstd = rsqrtf(var + 1e-5f);
    float4 gv = *(const float4*)(g + tid * 4);
    float4 bv = *(const float4*)(b + tid * 4);
    float4 o;
    o.x = (x.x - mu) * rstd * gv.x + bv.x;
    o.y = (x.y - mu) * rstd * gv.y + bv.y;
    o.z = (x.z - mu) * rstd * gv.z + bv.z;
    o.w = (x.w - mu) * rstd * gv.w + bv.w;
    *(float4*)(out + (size_t)row * DM + tid * 4) = o;
}

extern "C" void kernel_launch(void* const* d_in, const int* in_sizes, int n_in,
                              void* d_out, int out_size)
{
    const float* x   = (const float*)d_in[0];
    const int*   mask= (const int*)  d_in[1];
    const float* wq  = (const float*)d_in[2];
    const float* bq  = (const float*)d_in[3];
    const float* wk  = (const float*)d_in[4];
    const float* bk  = (const float*)d_in[5];
    const float* wv  = (const float*)d_in[6];
    const float* bv  = (const float*)d_in[7];
    const float* wo  = (const float*)d_in[8];
    const float* bo  = (const float*)d_in[9];
    const float* w1  = (const float*)d_in[10];
    const float* b1  = (const float*)d_in[11];
    const float* w2  = (const float*)d_in[12];
    const float* b2  = (const float*)d_in[13];
    const float* g1  = (const float*)d_in[14];
    const float* be1 = (const float*)d_in[15];
    const float* g2  = (const float*)d_in[16];
    const float* be2 = (const float*)d_in[17];
    float* out = (float*)d_out;

    float *q, *k, *v, *attn, *tmp, *x1, *hid;
    cudaGetSymbolAddress((void**)&q,    g_q);
    cudaGetSymbolAddress((void**)&k,    g_k);
    cudaGetSymbolAddress((void**)&v,    g_v);
    cudaGetSymbolAddress((void**)&attn, g_attn);
    cudaGetSymbolAddress((void**)&tmp,  g_tmp);
    cudaGetSymbolAddress((void**)&x1,   g_x1);
    cudaGetSymbolAddress((void**)&hid,  g_hid);

    static int smem_set = 0;
    if (!smem_set) {
        cudaFuncSetAttribute(k_flash, cudaFuncAttributeMaxDynamicSharedMemorySize, FLASH_SMEM);
        smem_set = 1;
    }

    // QKV projections
    k_qkv<<<dim3(DM / 64, S_LEN / 128, 3), 256>>>(x, wq, bq, wk, bk, wv, bv, q, k, v);
    // attention
    k_flash<<<dim3(S_LEN / 128, NH), 256, FLASH_SMEM>>>(q, k, v, mask, attn);
    // output projection + residual
    k_gemm128<<<dim3(DM / 128, S_LEN / 128), 256>>>(attn, wo, bo, x, tmp, DM, DM, 0);
    // LN1
    k_ln<<<S_LEN, 128>>>(tmp, g1, be1, x1);
    // FFN1 (+ReLU)
    k_gemm128<<<dim3(DF / 128, S_LEN / 128), 256>>>(x1, w1, b1, nullptr, hid, DF, DM, 1);
    // FFN2 + residual
    k_gemm128<<<dim3(DM / 128, S_LEN / 128), 256>>>(hid, w2, b2, x1, tmp, DM, DF, 0);
    // LN2 -> out
    k_ln<<<S_LEN, 128>>>(tmp, g2, be2, out);
}

// round 9
// speedup vs baseline: 1.2401x; 1.2401x over previous
#include <cuda_runtime.h>
#include <cuda_bf16.h>
#include <cstdint>

#define S_LEN 4096
#define DM    512
#define DF    2048
#define NH    8
#define DH    64

__device__ float g_q   [(size_t)S_LEN * DM];
__device__ float g_k   [(size_t)S_LEN * DM];
__device__ float g_v   [(size_t)S_LEN * DM];
__device__ float g_attn[(size_t)S_LEN * DM];
__device__ float g_tmp [(size_t)S_LEN * DM];
__device__ float g_x1  [(size_t)S_LEN * DM];
__device__ float g_hid [(size_t)S_LEN * DF];

// activation bf16 hi/lo scratch (max 8M elems for hid)
__device__ unsigned short g_ahi[(size_t)S_LEN * DF];
__device__ unsigned short g_alo[(size_t)S_LEN * DF];

// weights bf16 hi/lo, [N,K] K-major
#define OFF_Q 0
#define OFF_K 262144
#define OFF_V 524288
#define OFF_O 786432
#define OFF_1 1048576
#define OFF_2 2097152
#define W_TOT 3145728
__device__ unsigned short g_whi[W_TOT];
__device__ unsigned short g_wlo[W_TOT];

__device__ __forceinline__ uint32_t smem_u32(const void* p) {
    uint32_t a;
    asm("{ .reg .u64 t; cvta.to.shared.u64 t, %1; cvt.u32.u64 %0, t; }" : "=r"(a) : "l"(p));
    return a;
}
__device__ __forceinline__ uint32_t pk2(__nv_bfloat16 a, __nv_bfloat16 b) {
    return (uint32_t)__bfloat16_as_ushort(a) | ((uint32_t)__bfloat16_as_ushort(b) << 16);
}

#define CP_ASYNC16(s, g) \
    asm volatile("cp.async.cg.shared.global [%0], [%1], 16;" :: "r"(s), "l"(g) : "memory")
#define CP_COMMIT() asm volatile("cp.async.commit_group;" ::: "memory")
#define CP_WAIT1()  asm volatile("cp.async.wait_group 1;" ::: "memory")
#define CP_WAIT0()  asm volatile("cp.async.wait_group 0;" ::: "memory")

#define LDM4(r, a) \
    asm volatile("ldmatrix.sync.aligned.m8n8.x4.shared.b16 {%0,%1,%2,%3}, [%4];" \
        : "=r"((r)[0]), "=r"((r)[1]), "=r"((r)[2]), "=r"((r)[3]) : "r"(a))

#define MMA16816(d, a, b0, b1) \
    asm volatile("mma.sync.aligned.m16n8k16.row.col.f32.bf16.bf16.f32 " \
        "{%0,%1,%2,%3}, {%4,%5,%6,%7}, {%8,%9}, {%0,%1,%2,%3};" \
        : "+f"((d)[0]), "+f"((d)[1]), "+f"((d)[2]), "+f"((d)[3]) \
        : "r"((a)[0]), "r"((a)[1]), "r"((a)[2]), "r"((a)[3]), "r"(b0), "r"(b1))

// ---- weight convert: W[K,N] fp32 -> hi/lo bf16 [N,K] ----
__global__ void k_cvtw(const float* __restrict__ W, unsigned short* __restrict__ oh,
                       unsigned short* __restrict__ ol, int K, int N)
{
    __shared__ float t[32][33];
    int tx = threadIdx.x, ty = threadIdx.y;
    int k0 = blockIdx.x * 32, n0 = blockIdx.y * 32;
    t[ty][tx] = W[(size_t)(k0 + ty) * N + n0 + tx];
    __syncthreads();
    float v = t[tx][ty];
    __nv_bfloat16 h = __float2bfloat16(v);
    __nv_bfloat16 l = __float2bfloat16(v - __bfloat162float(h));
    size_t o = (size_t)(n0 + ty) * K + k0 + tx;
    oh[o] = __bfloat16_as_ushort(h);
    ol[o] = __bfloat16_as_ushort(l);
}

// ---- activation convert: fp32 [M,K] -> hi/lo bf16 [M,K] ----
__global__ void k_cvta(const float* __restrict__ in, unsigned short* __restrict__ oh,
                       unsigned short* __restrict__ ol)
{
    int i = blockIdx.x * 256 + threadIdx.x;
    float4 v = ((const float4*)in)[i];
    __nv_bfloat16 h0 = __float2bfloat16(v.x), h1 = __float2bfloat16(v.y);
    __nv_bfloat16 h2 = __float2bfloat16(v.z), h3 = __float2bfloat16(v.w);
    __nv_bfloat16 l0 = __float2bfloat16(v.x - __bfloat162float(h0));
    __nv_bfloat16 l1 = __float2bfloat16(v.y - __bfloat162float(h1));
    __nv_bfloat16 l2 = __float2bfloat16(v.z - __bfloat162float(h2));
    __nv_bfloat16 l3 = __float2bfloat16(v.w - __bfloat162float(h3));
    ((uint2*)oh)[i] = make_uint2(pk2(h0, h1), pk2(h2, h3));
    ((uint2*)ol)[i] = make_uint2(pk2(l0, l1), pk2(l2, l3));
}

// ---- mma.sync bf16-split GEMM core ----
// C[M,N] = A @ B^T, A hi/lo [M,K], B hi/lo [N,K]. CTA 128x128, 8 warps 32x64.
// smem stage: Ah 0, Al 18432, Bh 36864, Bl 55296 (row pitch 144B); 2 stages.
#define STG_SZ 73728
#define TG_SMEM (2 * STG_SZ)

__device__ __forceinline__ void gemm_core(
    const unsigned short* __restrict__ Ah, const unsigned short* __restrict__ Al,
    const unsigned short* __restrict__ Bh, const unsigned short* __restrict__ Bl,
    const float* __restrict__ bias, const float* __restrict__ res,
    float* __restrict__ C, int N, int K, int relu, int bm, int bn)
{
    extern __shared__ char smc[];
    const uint32_t sb = smem_u32(smc);
    const int tid = threadIdx.x, lane = tid & 31, wid = tid >> 5;
    const int wm = wid & 3, wn = wid >> 2;

    float acc[2][8][4];
    #pragma unroll
    for (int mi = 0; mi < 2; mi++)
        #pragma unroll
        for (int j = 0; j < 8; j++)
            #pragma unroll
            for (int e = 0; e < 4; e++) acc[mi][j][e] = 0.f;

    const int nk = K >> 6;

    auto issue = [&](int s) {
        int st = (s & 1) * STG_SZ;
        int k0 = s << 6;
        #pragma unroll
        for (int r = 0; r < 4; r++) {
            int id = tid + 256 * r, row = id >> 3, ch = id & 7;
            uint32_t so = sb + st + row * 144 + ch * 16;
            size_t ga = (size_t)(bm + row) * K + k0 + ch * 8;
            size_t gb = (size_t)(bn + row) * K + k0 + ch * 8;
            CP_ASYNC16(so,         Ah + ga);
            CP_ASYNC16(so + 18432, Al + ga);
            CP_ASYNC16(so + 36864, Bh + gb);
            CP_ASYNC16(so + 55296, Bl + gb);
        }
        CP_COMMIT();
    };

    issue(0);
    const uint32_t aoff = (wm * 32 + (lane & 15)) * 144 + (lane >> 4) * 16;
    const uint32_t boff = (wn * 64 + (lane & 15)) * 144 + (lane >> 4) * 16;

    for (int kt = 0; kt < nk; kt++) {
        if (kt + 1 < nk) { issue(kt + 1); CP_WAIT1(); }
        else             { CP_WAIT0(); }
        __syncthreads();

        const uint32_t base = sb + (kt & 1) * STG_SZ;
        #pragma unroll
        for (int ks = 0; ks < 4; ks++) {
            const uint32_t ko = ks * 32;
            uint32_t ahf[2][4], alf[2][4], bhf[4][4], blf[4][4];
            #pragma unroll
            for (int mi = 0; mi < 2; mi++) {
                LDM4(ahf[mi], base + aoff + mi * 2304 + ko);
                LDM4(alf[mi], base + 18432 + aoff + mi * 2304 + ko);
            }
            #pragma unroll
            for (int ni = 0; ni < 4; ni++) {
                LDM4(bhf[ni], base + 36864 + boff + ni * 2304 + ko);
                LDM4(blf[ni], base + 55296 + boff + ni * 2304 + ko);
            }
            #pragma unroll
            for (int mi = 0; mi < 2; mi++)
                #pragma unroll
                for (int ni = 0; ni < 4; ni++) {
                    MMA16816(acc[mi][2*ni],   ahf[mi], bhf[ni][0], bhf[ni][2]);
                    MMA16816(acc[mi][2*ni],   ahf[mi], blf[ni][0], blf[ni][2]);
                    MMA16816(acc[mi][2*ni],   alf[mi], bhf[ni][0], bhf[ni][2]);
                    MMA16816(acc[mi][2*ni+1], ahf[mi], bhf[ni][1], bhf[ni][3]);
                    MMA16816(acc[mi][2*ni+1], ahf[mi], blf[ni][1], blf[ni][3]);
                    MMA16816(acc[mi][2*ni+1], alf[mi], bhf[ni][1], bhf[ni][3]);
                }
        }
        __syncthreads();
    }

    // epilogue
    #pragma unroll
    for (int mi = 0; mi < 2; mi++) {
        int m0 = bm + wm * 32 + mi * 16 + (lane >> 2);
        #pragma unroll
        for (int j = 0; j < 8; j++) {
            int col = bn + wn * 64 + j * 8 + (lane & 3) * 2;
            float b0 = bias[col], b1 = bias[col + 1];
            float* d = acc[mi][j];
            float o0 = d[0] + b0, o1 = d[1] + b1;
            float o2 = d[2] + b0, o3 = d[3] + b1;
            if (relu) {
                o0 = fmaxf(o0, 0.f); o1 = fmaxf(o1, 0.f);
                o2 = fmaxf(o2, 0.f); o3 = fmaxf(o3, 0.f);
            }
            if (res) {
                o0 += res[(size_t)m0 * N + col];
                o1 += res[(size_t)m0 * N + col + 1];
                o2 += res[(size_t)(m0 + 8) * N + col];
                o3 += res[(size_t)(m0 + 8) * N + col + 1];
            }
            *(float2*)(C + (size_t)m0 * N + col)       = make_float2(o0, o1);
            *(float2*)(C + (size_t)(m0 + 8) * N + col) = make_float2(o2, o3);
        }
    }
}

__global__ void __launch_bounds__(256, 1) k_tgemm(
    const unsigned short* Ah, const unsigned short* Al,
    const unsigned short* Bh, const unsigned short* Bl,
    const float* bias, const float* res, float* C, int N, int K, int relu)
{
    gemm_core(Ah, Al, Bh, Bl, bias, res, C, N, K, relu,
              blockIdx.y * 128, blockIdx.x * 128);
}

__global__ void __launch_bounds__(256, 1) k_tqkv(
    const unsigned short* Ah, const unsigned short* Al,
    const unsigned short* Wh, const unsigned short* Wl,
    const float* bq, const float* bk, const float* bv,
    float* q, float* k, float* v)
{
    const unsigned short *Bh, *Bl; const float* bias; float* C;
    if (blockIdx.z == 0)      { Bh = Wh + OFF_Q; Bl = Wl + OFF_Q; bias = bq; C = q; }
    else if (blockIdx.z == 1) { Bh = Wh + OFF_K; Bl = Wl + OFF_K; bias = bk; C = k; }
    else                      { Bh = Wh + OFF_V; Bl = Wl + OFF_V; bias = bv; C = v; }
    gemm_core(Ah, Al, Bh, Bl, bias, nullptr, C, DM, DM, 0,
              blockIdx.y * 128, blockIdx.x * 128);
}

// ---- flash attention (fp32, proven) ----
#define FLASH_SMEM (64 * (132 + 68 + 68 + 132) * 4)

__global__ void __launch_bounds__(256, 2) k_flash(
    const float* __restrict__ q, const float* __restrict__ k,
    const float* __restrict__ v, const int* __restrict__ mask,
    float* __restrict__ out)
{
    extern __shared__ float smf[];
    float* Qt = smf;
    float* Ks = smf + 64 * 132;
    float* Vs = Ks + 64 * 68;
    float* Pt = Vs + 64 * 68;

    const int tid = threadIdx.x;
    const int tr = tid >> 4, tc = tid & 15;
    const int row0 = blockIdx.x * 128;
    const int dc0 = blockIdx.y * DH;

    #pragma unroll
    for (int r = 0; r < 8; r++) {
        int id = tid + 256 * r, row = id >> 4, c4 = id & 15;
        float4 t4 = *(const float4*)(q + (size_t)(row0 + row) * DM + dc0 + c4 * 4);
        Qt[(c4*4+0)*132+row] = t4.x; Qt[(c4*4+1)*132+row] = t4.y;
        Qt[(c4*4+2)*132+row] = t4.z; Qt[(c4*4+3)*132+row] = t4.w;
    }

    float acc[8][4], l[8];
    #pragma unroll
    for (int i = 0; i < 8; i++) {
        l[i] = 0.f;
        #pragma unroll
        for (int j = 0; j < 4; j++) acc[i][j] = 0.f;
    }

    for (int t0 = 0; t0 < S_LEN; t0 += 64) {
        __syncthreads();
        #pragma unroll
        for (int r = 0; r < 4; r++) {
            int id = tid + 256 * r, row = id >> 4, c4 = id & 15;
            *(float4*)(Ks + row * 68 + c4 * 4) =
                *(const float4*)(k + (size_t)(t0 + row) * DM + dc0 + c4 * 4);
            *(float4*)(Vs + row * 68 + c4 * 4) =
                *(const float4*)(v + (size_t)(t0 + row) * DM + dc0 + c4 * 4);
        }
        __syncthreads();

        float s[8][4];
        #pragma unroll
        for (int i = 0; i < 8; i++)
            #pragma unroll
            for (int j = 0; j < 4; j++) s[i][j] = 0.f;

        #pragma unroll 2
        for (int dcb = 0; dcb < 16; dcb++) {
            float kreg[4][4];
            #pragma unroll
            for (int j = 0; j < 4; j++) {
                float4 kf = *(const float4*)(Ks + (4*tc + j) * 68 + dcb * 4);
                kreg[j][0]=kf.x; kreg[j][1]=kf.y; kreg[j][2]=kf.z; kreg[j][3]=kf.w;
            }
            #pragma unroll
            for (int m = 0; m < 4; m++) {
                const float* qp = Qt + (dcb*4 + m) * 132 + 8 * tr;
                float4 qa = *(const float4*)qp;
                float4 qb = *(const float4*)(qp + 4);
                float qf[8] = {qa.x,qa.y,qa.z,qa.w,qb.x,qb.y,qb.z,qb.w};
                #pragma unroll
                for (int i = 0; i < 8; i++)
                    #pragma unroll
                    for (int j = 0; j < 4; j++)
                        s[i][j] += qf[i] * kreg[j][m];
            }
        }

        float p[8][4];
        #pragma unroll
        for (int i = 0; i < 8; i++) {
            int4 mv = *(const int4*)(mask + (size_t)(row0 + 8*tr + i) * S_LEN + t0 + 4*tc);
            p[i][0] = mv.x ? __expf(s[i][0]) : 0.f;
            p[i][1] = mv.y ? __expf(s[i][1]) : 0.f;
            p[i][2] = mv.z ? __expf(s[i][2]) : 0.f;
            p[i][3] = mv.w ? __expf(s[i][3]) : 0.f;
            l[i] += p[i][0] + p[i][1] + p[i][2] + p[i][3];
        }
        #pragma unroll
        for (int j = 0; j < 4; j++) {
            float* pp = Pt + (4*tc + j) * 132 + 8 * tr;
            *(float4*)pp       = make_float4(p[0][j], p[1][j], p[2][j], p[3][j]);
            *(float4*)(pp + 4) = make_float4(p[4][j], p[5][j], p[6][j], p[7][j]);
        }
        __syncthreads();

        #pragma unroll 4
        for (int t = 0; t < 64; t++) {
            const float* pp = Pt + t * 132 + 8 * tr;
            float4 pa = *(const float4*)pp;
            float4 pb = *(const float4*)(pp + 4);
            float4 vf = *(const float4*)(Vs + t * 68 + 4 * tc);
            float pf[8] = {pa.x,pa.y,pa.z,pa.w,pb.x,pb.y,pb.z,pb.w};
            #pragma unroll
            for (int i = 0; i < 8; i++) {
                acc[i][0] += pf[i] * vf.x; acc[i][1] += pf[i] * vf.y;
                acc[i][2] += pf[i] * vf.z; acc[i][3] += pf[i] * vf.w;
            }
        }
    }

    #pragma unroll
    for (int i = 0; i < 8; i++) {
        float li = l[i];
        li += __shfl_xor_sync(0xffffffffu, li, 1);
        li += __shfl_xor_sync(0xffffffffu, li, 2);
        li += __shfl_xor_sync(0xffffffffu, li, 4);
        li += __shfl_xor_sync(0xffffffffu, li, 8);
        float inv = 1.0f / li;
        *(float4*)(out + (size_t)(row0 + 8*tr + i) * DM + dc0 + 4*tc) =
            make_float4(acc[i][0]*inv, acc[i][1]*inv, acc[i][2]*inv, acc[i][3]*inv);
    }
}

// ---- layernorm ----
__global__ void __launch_bounds__(128) k_ln(
    const float* __restrict__ in, const float* __restrict__ g,
    const float* __restrict__ b, float* __restrict__ out)
{
    const int row = blockIdx.x, tid = threadIdx.x;
    float4 x = *(const float4*)(in + (size_t)row * DM + tid * 4);
    float s  = x.x + x.y + x.z + x.w;
    float ss = x.x*x.x + x.y*x.y + x.z*x.z + x.w*x.w;
    #pragma unroll
    for (int m = 16; m > 0; m >>= 1) {
        s  += __shfl_xor_sync(0xffffffffu, s, m);
        ss += __shfl_xor_sync(0xffffffffu, ss, m);
    }
    __shared__ float red[8];
    int wid = tid >> 5, lane = tid & 31;
    if (lane == 0) { red[wid] = s; red[4 + wid] = ss; }
    __syncthreads();
    s  = red[0] + red[1] + red[2] + red[3];
    ss = red[4] + red[5] + red[6] + red[7];
    float mu = s * (1.f / DM);
    float var = ss * (1.f / DM) - mu * mu;
    float rstd = rsqrtf(var + 1e-5f);
    float4 gv = *(const float4*)(g + tid * 4);
    float4 bv = *(const float4*)(b + tid * 4);
    float4 o;
    o.x = (x.x - mu) * rstd * gv.x + bv.x;
    o.y = (x.y - mu) * rstd * gv.y + bv.y;
    o.z = (x.z - mu) * rstd * gv.z + bv.z;
    o.w = (x.w - mu) * rstd * gv.w + bv.w;
    *(float4*)(out + (size_t)row * DM + tid * 4) = o;
}

extern "C" void kernel_launch(void* const* d_in, const int* in_sizes, int n_in,
                              void* d_out, int out_size)
{
    const float* x   = (const float*)d_in[0];
    const int*   mask= (const int*)  d_in[1];
    const float* wq  = (const float*)d_in[2];
    const float* bq  = (const float*)d_in[3];
    const float* wk  = (const float*)d_in[4];
    const float* bk  = (const float*)d_in[5];
    const float* wv  = (const float*)d_in[6];
    const float* bv  = (const float*)d_in[7];
    const float* wo  = (const float*)d_in[8];
    const float* bo  = (const float*)d_in[9];
    const float* w1  = (const float*)d_in[10];
    const float* b1  = (const float*)d_in[11];
    const float* w2  = (const float*)d_in[12];
    const float* b2  = (const float*)d_in[13];
    const float* g1  = (const float*)d_in[14];
    const float* be1 = (const float*)d_in[15];
    const float* g2  = (const float*)d_in[16];
    const float* be2 = (const float*)d_in[17];
    float* out = (float*)d_out;

    float *q, *k, *v, *attn, *tmp, *x1, *hid;
    unsigned short *whi, *wlo, *ahi, *alo;
    cudaGetSymbolAddress((void**)&q,    g_q);
    cudaGetSymbolAddress((void**)&k,    g_k);
    cudaGetSymbolAddress((void**)&v,    g_v);
    cudaGetSymbolAddress((void**)&attn, g_attn);
    cudaGetSymbolAddress((void**)&tmp,  g_tmp);
    cudaGetSymbolAddress((void**)&x1,   g_x1);
    cudaGetSymbolAddress((void**)&hid,  g_hid);
    cudaGetSymbolAddress((void**)&whi,  g_whi);
    cudaGetSymbolAddress((void**)&wlo,  g_wlo);
    cudaGetSymbolAddress((void**)&ahi,  g_ahi);
    cudaGetSymbolAddress((void**)&alo,  g_alo);

    cudaFuncSetAttribute(k_flash, cudaFuncAttributeMaxDynamicSharedMemorySize, FLASH_SMEM);
    cudaFuncSetAttribute(k_tgemm, cudaFuncAttributeMaxDynamicSharedMemorySize, TG_SMEM);
    cudaFuncSetAttribute(k_tqkv,  cudaFuncAttributeMaxDynamicSharedMemorySize, TG_SMEM);

    dim3 b32(32, 32);
    k_cvtw<<<dim3(16, 16), b32>>>(wq, whi + OFF_Q, wlo + OFF_Q, DM, DM);
    k_cvtw<<<dim3(16, 16), b32>>>(wk, whi + OFF_K, wlo + OFF_K, DM, DM);
    k_cvtw<<<dim3(16, 16), b32>>>(wv, whi + OFF_V, wlo + OFF_V, DM, DM);
    k_cvtw<<<dim3(16, 16), b32>>>(wo, whi + OFF_O, wlo + OFF_O, DM, DM);
    k_cvtw<<<dim3(16, 64), b32>>>(w1, whi + OFF_1, wlo + OFF_1, DM, DF);
    k_cvtw<<<dim3(64, 16), b32>>>(w2, whi + OFF_2, wlo + OFF_2, DF, DM);

    const int N4_DM = S_LEN * DM / 4 / 256;   // 2048 blocks
    const int N4_DF = S_LEN * DF / 4 / 256;   // 8192 blocks

    // QKV
    k_cvta<<<N4_DM, 256>>>(x, ahi, alo);
    k_tqkv<<<dim3(DM/128, S_LEN/128, 3), 256, TG_SMEM>>>(ahi, alo, whi, wlo, bq, bk, bv, q, k, v);
    // attention
    k_flash<<<dim3(S_LEN/128, NH), 256, FLASH_SMEM>>>(q, k, v, mask, attn);
    // Wo + residual
    k_cvta<<<N4_DM, 256>>>(attn, ahi, alo);
    k_tgemm<<<dim3(DM/128, S_LEN/128), 256, TG_SMEM>>>(ahi, alo, whi+OFF_O, wlo+OFF_O, bo, x, tmp, DM, DM, 0);
    // LN1
    k_ln<<<S_LEN, 128>>>(tmp, g1, be1, x1);
    // FFN1 (+ReLU)
    k_cvta<<<N4_DM, 256>>>(x1, ahi, alo);
    k_tgemm<<<dim3(DF/128, S_LEN/128), 256, TG_SMEM>>>(ahi, alo, whi+OFF_1, wlo+OFF_1, b1, nullptr, hid, DF, DM, 1);
    // FFN2 + residual
    k_cvta<<<N4_DF, 256>>>(hid, ahi, alo);
    k_tgemm<<<dim3(DM/128, S_LEN/128), 256, TG_SMEM>>>(ahi, alo, whi+OFF_2, wlo+OFF_2, b2, x1, tmp, DM, DF, 0);
    // LN2 -> out
    k_ln<<<S_LEN, 128>>>(tmp, g2, be2, out);
}